// round 2
// baseline (speedup 1.0000x reference)
#include <cuda_runtime.h>
#include <cuda_bf16.h>
#include <cstdint>

#define NNODES 100000
#define HID 128
#define NGRAPH 64

// ---------------- scratch (static device globals; no allocation) ------------
__device__ float g_bufA[NNODES * HID];   // xw (gemm output)
__device__ float g_bufB[NNODES * HID];   // aggregation target
__device__ float g_bufC[NNODES * HID];   // post BN+ReLU activations
__device__ float g_dinv[NNODES];         // deg, then rsqrt(deg)
__device__ float g_stats[2 * HID];       // colsum, colsumsq
__device__ float g_pooled[NGRAPH * HID];
__device__ float g_counts[NGRAPH];

// ---------------- degree ----------------------------------------------------
__global__ void deg_init(float* deg, int n) {
    int i = blockIdx.x * blockDim.x + threadIdx.x;
    if (i < n) deg[i] = 1.0f;  // self loop
}

__global__ void deg_count(const int* __restrict__ dst, float* deg, int E) {
    int e = blockIdx.x * blockDim.x + threadIdx.x;
    if (e < E) atomicAdd(&deg[dst[e]], 1.0f);
}

__global__ void deg_finalize(float* deg, int n) {
    int i = blockIdx.x * blockDim.x + threadIdx.x;
    if (i < n) deg[i] = rsqrtf(deg[i]);  // deg >= 1 always
}

// ---------------- GEMM: out[n,128] = A[n,128] @ W[128,128] ------------------
// Block: 256 threads, 64 rows per block. W processed in 4 chunks of 32 cols.
__global__ __launch_bounds__(256) void gemm128(
    const float* __restrict__ A, const float* __restrict__ W,
    float* __restrict__ out, int n, int nanclean)
{
    __shared__ __align__(16) float As[64 * 128];
    __shared__ float Ws[128 * 32];

    int r0 = blockIdx.x * 64;
    // load A tile (zero-pad rows past n)
    for (int i = threadIdx.x; i < 64 * 128 / 4; i += 256) {
        int idx = i * 4;
        int r = idx >> 7;
        float4 v = make_float4(0.f, 0.f, 0.f, 0.f);
        if (r0 + r < n)
            v = *(const float4*)(A + (size_t)(r0 + r) * 128 + (idx & 127));
        if (nanclean) {
            v.x = (v.x == v.x) ? v.x : 0.f;
            v.y = (v.y == v.y) ? v.y : 0.f;
            v.z = (v.z == v.z) ? v.z : 0.f;
            v.w = (v.w == v.w) ? v.w : 0.f;
        }
        *(float4*)(As + idx) = v;
    }

    int col = threadIdx.x & 31;
    int rg  = threadIdx.x >> 5;  // 0..7 (8 rows each)

    for (int cc = 0; cc < 4; cc++) {
        __syncthreads();
        for (int i = threadIdx.x; i < 128 * 32; i += 256) {
            int k = i >> 5, c = i & 31;
            Ws[i] = W[k * 128 + cc * 32 + c];
        }
        __syncthreads();

        float acc[8] = {0.f, 0.f, 0.f, 0.f, 0.f, 0.f, 0.f, 0.f};
        #pragma unroll
        for (int k = 0; k < 128; k += 4) {
            float w0 = Ws[(k + 0) * 32 + col];
            float w1 = Ws[(k + 1) * 32 + col];
            float w2 = Ws[(k + 2) * 32 + col];
            float w3 = Ws[(k + 3) * 32 + col];
            #pragma unroll
            for (int r = 0; r < 8; r++) {
                float4 a = *(const float4*)&As[(rg * 8 + r) * 128 + k];
                acc[r] += a.x * w0 + a.y * w1 + a.z * w2 + a.w * w3;
            }
        }
        #pragma unroll
        for (int r = 0; r < 8; r++) {
            int row = r0 + rg * 8 + r;
            if (row < n) out[(size_t)row * 128 + cc * 32 + col] = acc[r];
        }
    }
}

// ---------------- aggregation ------------------------------------------------
// agg[i] = xw[i] * dinv[i]^2   (self loop term)
__global__ void self_init(const float* __restrict__ xw, const float* __restrict__ dinv,
                          float* __restrict__ agg, int n)
{
    int i = blockIdx.x * blockDim.x + threadIdx.x;
    if (i < n * HID) {
        int r = i >> 7;
        float d = dinv[r];
        agg[i] = xw[i] * d * d;
    }
}

// one warp per edge; lane handles 4 contiguous floats (float4 read, 4 atomics)
__global__ __launch_bounds__(256) void edge_scatter(
    const float* __restrict__ xw, const int* __restrict__ src,
    const int* __restrict__ dst_idx,
    const float* __restrict__ dinv, float* __restrict__ agg, int E)
{
    int e = blockIdx.x * 8 + (threadIdx.x >> 5);
    if (e >= E) return;
    int lane = threadIdx.x & 31;
    int s = src[e];
    int d = dst_idx[e];
    float c = dinv[s] * dinv[d];
    float4 v = *(const float4*)(xw + (size_t)s * 128 + lane * 4);
    float* dst = agg + (size_t)d * 128 + lane * 4;
    atomicAdd(dst + 0, v.x * c);
    atomicAdd(dst + 1, v.y * c);
    atomicAdd(dst + 2, v.z * c);
    atomicAdd(dst + 3, v.w * c);
}

// ---------------- batchnorm --------------------------------------------------
__global__ void zero_kernel(float* p, int n) {
    int i = blockIdx.x * blockDim.x + threadIdx.x;
    if (i < n) p[i] = 0.f;
}

__global__ __launch_bounds__(128) void bn_stats(
    const float* __restrict__ src, float* __restrict__ stats, int n)
{
    int col = threadIdx.x;  // 128 threads
    float s = 0.f, s2 = 0.f;
    for (int r = blockIdx.x; r < n; r += gridDim.x) {
        float v = src[(size_t)r * 128 + col];
        s += v; s2 += v * v;
    }
    atomicAdd(&stats[col], s);
    atomicAdd(&stats[128 + col], s2);
}

__global__ __launch_bounds__(128) void bn_relu(
    const float* __restrict__ src, const float* __restrict__ stats,
    const float* __restrict__ gamma, const float* __restrict__ beta,
    float* __restrict__ dst, int n)
{
    int col = threadIdx.x;
    float invn = 1.0f / (float)n;
    float mean = stats[col] * invn;
    float var  = stats[128 + col] * invn - mean * mean;
    float sc = rsqrtf(var + 1e-5f) * gamma[col];
    float sh = beta[col] - mean * sc;
    for (int r = blockIdx.x; r < n; r += gridDim.x) {
        float v = src[(size_t)r * 128 + col] * sc + sh;
        dst[(size_t)r * 128 + col] = fmaxf(v, 0.f);
    }
}

// ---------------- pooling ----------------------------------------------------
__global__ __launch_bounds__(256) void counts_kernel(
    const int* __restrict__ batch, float* __restrict__ counts, int n)
{
    __shared__ float sc[NGRAPH];
    if (threadIdx.x < NGRAPH) sc[threadIdx.x] = 0.f;
    __syncthreads();
    for (int i = blockIdx.x * blockDim.x + threadIdx.x; i < n; i += gridDim.x * blockDim.x)
        atomicAdd(&sc[batch[i]], 1.0f);
    __syncthreads();
    if (threadIdx.x < NGRAPH) atomicAdd(&counts[threadIdx.x], sc[threadIdx.x]);
}

// batch is sorted: run-length accumulate per block, flush at boundaries
__global__ __launch_bounds__(128) void pool_kernel(
    const float* __restrict__ h, const int* __restrict__ batch,
    float* __restrict__ pooled, int n)
{
    int col = threadIdx.x;
    int r0 = blockIdx.x * 128;
    if (r0 >= n) return;
    int r1 = min(r0 + 128, n);
    int cg = batch[r0];
    float acc = 0.f;
    for (int r = r0; r < r1; r++) {
        int g = batch[r];
        if (g != cg) {
            atomicAdd(&pooled[cg * 128 + col], acc);
            acc = 0.f;
            cg = g;
        }
        acc += h[(size_t)r * 128 + col];
    }
    atomicAdd(&pooled[cg * 128 + col], acc);
}

// ---------------- classifier (single block) ----------------------------------
__global__ __launch_bounds__(256) void classifier_kernel(
    const float* __restrict__ pooled, const float* __restrict__ counts,
    const float* __restrict__ Wc1, const float* __restrict__ bc1,
    const float* __restrict__ Wc2, const float* __restrict__ bc2,
    float* __restrict__ out)
{
    __shared__ float Z[64 * 64];
    __shared__ float inv[NGRAPH];
    int tid = threadIdx.x;
    if (tid < NGRAPH) inv[tid] = 1.0f / fmaxf(counts[tid], 1.0f);
    __syncthreads();

    for (int idx = tid; idx < 64 * 64; idx += 256) {
        int r = idx >> 6, c = idx & 63;
        float dot = 0.f;
        #pragma unroll 8
        for (int k = 0; k < 128; k++)
            dot += pooled[r * 128 + k] * Wc1[k * 64 + c];
        Z[idx] = fmaxf(dot * inv[r] + bc1[c], 0.f);
    }
    __syncthreads();

    for (int idx = tid; idx < 128; idx += 256) {
        int r = idx >> 1, c = idx & 1;
        float dot = bc2[c];
        #pragma unroll
        for (int k = 0; k < 64; k++)
            dot += Z[r * 64 + k] * Wc2[k * 2 + c];
        out[idx] = (dot == dot) ? dot : 0.f;  // nan_to_num
    }
}

// ---------------- launch ------------------------------------------------------
extern "C" void kernel_launch(void* const* d_in, const int* in_sizes, int n_in,
                              void* d_out, int out_size)
{
    const float* x     = (const float*)d_in[0];
    const int*   ei    = (const int*)d_in[1];     // int32! (JAX x64 disabled)
    const int*   batch = (const int*)d_in[2];
    const float* W1  = (const float*)d_in[3];
    // b1 = d_in[4]  — exactly cancelled by BatchNorm (per-column constant shift)
    const float* g1  = (const float*)d_in[5];
    const float* be1 = (const float*)d_in[6];
    const float* W2  = (const float*)d_in[7];
    // b2 = d_in[8]  — same
    const float* g2  = (const float*)d_in[9];
    const float* be2 = (const float*)d_in[10];
    const float* Wc1 = (const float*)d_in[11];
    const float* bc1 = (const float*)d_in[12];
    const float* Wc2 = (const float*)d_in[13];
    const float* bc2 = (const float*)d_in[14];
    float* out = (float*)d_out;

    int n = in_sizes[0] / HID;
    int E = in_sizes[1] / 2;
    const int* src = ei;
    const int* dst = ei + E;

    float *bufA, *bufB, *bufC, *dinv, *stats, *pooled, *counts;
    cudaGetSymbolAddress((void**)&bufA,   g_bufA);
    cudaGetSymbolAddress((void**)&bufB,   g_bufB);
    cudaGetSymbolAddress((void**)&bufC,   g_bufC);
    cudaGetSymbolAddress((void**)&dinv,   g_dinv);
    cudaGetSymbolAddress((void**)&stats,  g_stats);
    cudaGetSymbolAddress((void**)&pooled, g_pooled);
    cudaGetSymbolAddress((void**)&counts, g_counts);

    int nb256 = (n + 255) / 256;
    int eb256 = (E + 255) / 256;
    int gemm_blocks = (n + 63) / 64;
    int scat_blocks = (E + 7) / 8;
    int elem_blocks = (n * HID + 255) / 256;

    // degrees (shared by both layers)
    deg_init<<<nb256, 256>>>(dinv, n);
    deg_count<<<eb256, 256>>>(dst, dinv, E);
    deg_finalize<<<nb256, 256>>>(dinv, n);

    // ---- layer 1 ----
    gemm128<<<gemm_blocks, 256>>>(x, W1, bufA, n, 1);
    self_init<<<elem_blocks, 256>>>(bufA, dinv, bufB, n);
    edge_scatter<<<scat_blocks, 256>>>(bufA, src, dst, dinv, bufB, E);
    zero_kernel<<<1, 256>>>(stats, 256);
    bn_stats<<<512, 128>>>(bufB, stats, n);
    bn_relu<<<512, 128>>>(bufB, stats, g1, be1, bufC, n);

    // ---- layer 2 ----
    gemm128<<<gemm_blocks, 256>>>(bufC, W2, bufA, n, 0);
    self_init<<<elem_blocks, 256>>>(bufA, dinv, bufB, n);
    edge_scatter<<<scat_blocks, 256>>>(bufA, src, dst, dinv, bufB, E);
    zero_kernel<<<1, 256>>>(stats, 256);
    bn_stats<<<512, 128>>>(bufB, stats, n);
    bn_relu<<<512, 128>>>(bufB, stats, g2, be2, bufC, n);

    // ---- pool + classifier ----
    zero_kernel<<<(NGRAPH * HID + 255) / 256, 256>>>(pooled, NGRAPH * HID);
    zero_kernel<<<1, 64>>>(counts, NGRAPH);
    counts_kernel<<<64, 256>>>(batch, counts, n);
    pool_kernel<<<(n + 127) / 128, 128>>>(bufC, batch, pooled, n);
    classifier_kernel<<<1, 256>>>(pooled, counts, Wc1, bc1, Wc2, bc2, out);
}

// round 3
// speedup vs baseline: 1.8304x; 1.8304x over previous
#include <cuda_runtime.h>
#include <cuda_bf16.h>
#include <cstdint>

#define NNODES 100000
#define HID 128
#define NGRAPH 64

// ---------------- scratch (device globals; float4 for 16B alignment) --------
__device__ float4 g_bufA4[NNODES * HID / 4];   // y = xw * dinv[row]
__device__ float4 g_bufB4[NNODES * HID / 4];   // aggregation target (layer 1)
__device__ float4 g_bufC4[NNODES * HID / 4];   // aggregation target (layer 2)
__device__ float  g_dinv[NNODES];              // deg -> rsqrt(deg)
__device__ float  g_stats[2 * HID];            // colsum, colsumsq
__device__ float  g_scsh[2 * HID];             // BN scale / shift
__device__ float  g_pooled[NGRAPH * HID];
__device__ float  g_counts[NGRAPH];

// ---------------- degree ----------------------------------------------------
__global__ void deg_init(float* deg, int n) {
    int i = blockIdx.x * blockDim.x + threadIdx.x;
    if (i < n) deg[i] = 1.0f;  // self loop
}

__global__ void deg_count(const int* __restrict__ dst, float* deg, int E) {
    int e = blockIdx.x * blockDim.x + threadIdx.x;
    if (e < E) atomicAdd(&deg[dst[e]], 1.0f);
}

__global__ void deg_finalize(float* deg, int n) {
    int i = blockIdx.x * blockDim.x + threadIdx.x;
    if (i < n) deg[i] = rsqrtf(deg[i]);  // deg >= 1 always
}

// ---------------- fused GEMM ------------------------------------------------
// out: y[row] = (f(A)[row] @ W) * dinv[row];  agg[row] = y[row] * dinv[row]
// f = identity / nan_to_num (mode 1) / BN+ReLU via scsh (mode 2)
// 256 threads: warp rg owns rows rg*8..+7, lane cg owns cols cg*4..+3.
__global__ __launch_bounds__(256) void gemm128(
    const float* __restrict__ A, const float* __restrict__ W,
    const float* __restrict__ scsh, const float* __restrict__ dinv,
    float* __restrict__ y, float* __restrict__ agg, int n, int mode)
{
    __shared__ __align__(16) float As[64 * 32];
    __shared__ __align__(16) float Ws[32 * 128];

    int r0 = blockIdx.x * 64;
    int tid = threadIdx.x;
    int cg = tid & 31;
    int rg = tid >> 5;

    float acc[8][4];
    #pragma unroll
    for (int r = 0; r < 8; r++)
        #pragma unroll
        for (int j = 0; j < 4; j++) acc[r][j] = 0.f;

    for (int kc = 0; kc < 4; kc++) {
        // A tile: 64 rows x 32 k  (512 float4, 2 per thread)
        #pragma unroll
        for (int t = 0; t < 2; t++) {
            int i = tid + t * 256;
            int r = i >> 3;
            int k4 = (i & 7) * 4;
            float4 v = make_float4(0.f, 0.f, 0.f, 0.f);
            if (r0 + r < n)
                v = *(const float4*)(A + (size_t)(r0 + r) * 128 + kc * 32 + k4);
            if (mode == 1) {
                v.x = (v.x == v.x) ? v.x : 0.f;
                v.y = (v.y == v.y) ? v.y : 0.f;
                v.z = (v.z == v.z) ? v.z : 0.f;
                v.w = (v.w == v.w) ? v.w : 0.f;
            } else if (mode == 2) {
                int c = kc * 32 + k4;
                v.x = fmaxf(v.x * scsh[c + 0] + scsh[128 + c + 0], 0.f);
                v.y = fmaxf(v.y * scsh[c + 1] + scsh[128 + c + 1], 0.f);
                v.z = fmaxf(v.z * scsh[c + 2] + scsh[128 + c + 2], 0.f);
                v.w = fmaxf(v.w * scsh[c + 3] + scsh[128 + c + 3], 0.f);
            }
            *(float4*)(As + r * 32 + k4) = v;
        }
        // W tile: 32 k x 128 cols  (1024 float4, 4 per thread)
        #pragma unroll
        for (int t = 0; t < 4; t++) {
            int i = tid + t * 256;
            int k = i >> 5, c4 = (i & 31) * 4;
            *(float4*)(Ws + k * 128 + c4) =
                *(const float4*)(W + (size_t)(kc * 32 + k) * 128 + c4);
        }
        __syncthreads();

        #pragma unroll
        for (int k = 0; k < 32; k++) {
            float4 w = *(float4*)(Ws + k * 128 + cg * 4);   // conflict-free LDS.128
            #pragma unroll
            for (int r = 0; r < 8; r++) {
                float a = As[(rg * 8 + r) * 32 + k];        // warp broadcast
                acc[r][0] += a * w.x;
                acc[r][1] += a * w.y;
                acc[r][2] += a * w.z;
                acc[r][3] += a * w.w;
            }
        }
        __syncthreads();
    }

    #pragma unroll
    for (int r = 0; r < 8; r++) {
        int row = r0 + rg * 8 + r;
        if (row < n) {
            float di = dinv[row];
            float4 v = make_float4(acc[r][0] * di, acc[r][1] * di,
                                   acc[r][2] * di, acc[r][3] * di);
            *(float4*)(y + (size_t)row * 128 + cg * 4) = v;
            float4 s = make_float4(v.x * di, v.y * di, v.z * di, v.w * di);
            *(float4*)(agg + (size_t)row * 128 + cg * 4) = s;
        }
    }
}

// ---------------- edge scatter: agg[d] += y[s] * dinv[d] (vector red) -------
__global__ __launch_bounds__(256) void edge_scatter(
    const float* __restrict__ y, const int* __restrict__ src,
    const int* __restrict__ dst_idx,
    const float* __restrict__ dinv, float* __restrict__ agg, int E)
{
    int e = blockIdx.x * 8 + (threadIdx.x >> 5);
    if (e >= E) return;
    int lane = threadIdx.x & 31;
    int s = __ldg(src + e);
    int d = __ldg(dst_idx + e);
    float c = dinv[d];
    float4 v = *(const float4*)(y + (size_t)s * 128 + lane * 4);
    float* p = agg + (size_t)d * 128 + lane * 4;
    asm volatile("red.global.add.v4.f32 [%0], {%1, %2, %3, %4};"
                 :: "l"(p), "f"(v.x * c), "f"(v.y * c), "f"(v.z * c), "f"(v.w * c)
                 : "memory");
}

// ---------------- batchnorm --------------------------------------------------
__global__ void zero_kernel(float* p, int n) {
    int i = blockIdx.x * blockDim.x + threadIdx.x;
    if (i < n) p[i] = 0.f;
}

__global__ __launch_bounds__(128) void bn_stats(
    const float* __restrict__ src, float* __restrict__ stats, int n)
{
    int col = threadIdx.x;
    float s = 0.f, s2 = 0.f;
    for (int r = blockIdx.x; r < n; r += gridDim.x) {
        float v = src[(size_t)r * 128 + col];
        s += v; s2 += v * v;
    }
    atomicAdd(&stats[col], s);
    atomicAdd(&stats[128 + col], s2);
}

__global__ void bn_finalize(
    const float* __restrict__ stats, const float* __restrict__ gamma,
    const float* __restrict__ beta, float* __restrict__ scsh, int n)
{
    int c = threadIdx.x;  // 128 threads
    float invn = 1.0f / (float)n;
    float mean = stats[c] * invn;
    float var  = stats[128 + c] * invn - mean * mean;
    float sc = rsqrtf(var + 1e-5f) * gamma[c];
    scsh[c] = sc;
    scsh[128 + c] = beta[c] - mean * sc;
}

// ---------------- pooling (BN+ReLU fused; batch sorted -> run length) --------
__global__ __launch_bounds__(256) void counts_kernel(
    const int* __restrict__ batch, float* __restrict__ counts, int n)
{
    __shared__ float sc[NGRAPH];
    if (threadIdx.x < NGRAPH) sc[threadIdx.x] = 0.f;
    __syncthreads();
    for (int i = blockIdx.x * blockDim.x + threadIdx.x; i < n; i += gridDim.x * blockDim.x)
        atomicAdd(&sc[batch[i]], 1.0f);
    __syncthreads();
    if (threadIdx.x < NGRAPH) atomicAdd(&counts[threadIdx.x], sc[threadIdx.x]);
}

__global__ __launch_bounds__(128) void pool_kernel(
    const float* __restrict__ agg, const float* __restrict__ scsh,
    const int* __restrict__ batch, float* __restrict__ pooled, int n)
{
    int col = threadIdx.x;
    float sc = scsh[col], sh = scsh[128 + col];
    int r0 = blockIdx.x * 128;
    if (r0 >= n) return;
    int r1 = min(r0 + 128, n);
    int cg = batch[r0];
    float acc = 0.f;
    for (int r = r0; r < r1; r++) {
        int g = batch[r];
        if (g != cg) {
            atomicAdd(&pooled[cg * 128 + col], acc);
            acc = 0.f;
            cg = g;
        }
        acc += fmaxf(agg[(size_t)r * 128 + col] * sc + sh, 0.f);
    }
    atomicAdd(&pooled[cg * 128 + col], acc);
}

// ---------------- classifier (single block) ----------------------------------
__global__ __launch_bounds__(256) void classifier_kernel(
    const float* __restrict__ pooled, const float* __restrict__ counts,
    const float* __restrict__ Wc1, const float* __restrict__ bc1,
    const float* __restrict__ Wc2, const float* __restrict__ bc2,
    float* __restrict__ out)
{
    __shared__ float Z[64 * 64];
    __shared__ float inv[NGRAPH];
    int tid = threadIdx.x;
    if (tid < NGRAPH) inv[tid] = 1.0f / fmaxf(counts[tid], 1.0f);
    __syncthreads();

    for (int idx = tid; idx < 64 * 64; idx += 256) {
        int r = idx >> 6, c = idx & 63;
        float dot = 0.f;
        #pragma unroll 8
        for (int k = 0; k < 128; k++)
            dot += pooled[r * 128 + k] * Wc1[k * 64 + c];
        Z[idx] = fmaxf(dot * inv[r] + bc1[c], 0.f);
    }
    __syncthreads();

    for (int idx = tid; idx < 128; idx += 256) {
        int r = idx >> 1, c = idx & 1;
        float dot = bc2[c];
        #pragma unroll
        for (int k = 0; k < 64; k++)
            dot += Z[r * 64 + k] * Wc2[k * 2 + c];
        out[idx] = (dot == dot) ? dot : 0.f;  // nan_to_num
    }
}

// ---------------- launch ------------------------------------------------------
extern "C" void kernel_launch(void* const* d_in, const int* in_sizes, int n_in,
                              void* d_out, int out_size)
{
    const float* x     = (const float*)d_in[0];
    const int*   ei    = (const int*)d_in[1];
    const int*   batch = (const int*)d_in[2];
    const float* W1  = (const float*)d_in[3];
    // b1 = d_in[4] — exactly cancelled by BatchNorm
    const float* g1  = (const float*)d_in[5];
    const float* be1 = (const float*)d_in[6];
    const float* W2  = (const float*)d_in[7];
    // b2 = d_in[8] — same
    const float* g2  = (const float*)d_in[9];
    const float* be2 = (const float*)d_in[10];
    const float* Wc1 = (const float*)d_in[11];
    const float* bc1 = (const float*)d_in[12];
    const float* Wc2 = (const float*)d_in[13];
    const float* bc2 = (const float*)d_in[14];
    float* out = (float*)d_out;

    int n = in_sizes[0] / HID;
    int E = in_sizes[1] / 2;
    const int* src = ei;
    const int* dst = ei + E;

    float *bufA, *bufB, *bufC, *dinv, *stats, *scsh, *pooled, *counts;
    cudaGetSymbolAddress((void**)&bufA,   g_bufA4);
    cudaGetSymbolAddress((void**)&bufB,   g_bufB4);
    cudaGetSymbolAddress((void**)&bufC,   g_bufC4);
    cudaGetSymbolAddress((void**)&dinv,   g_dinv);
    cudaGetSymbolAddress((void**)&stats,  g_stats);
    cudaGetSymbolAddress((void**)&scsh,   g_scsh);
    cudaGetSymbolAddress((void**)&pooled, g_pooled);
    cudaGetSymbolAddress((void**)&counts, g_counts);

    int nb256 = (n + 255) / 256;
    int eb256 = (E + 255) / 256;
    int gemm_blocks = (n + 63) / 64;
    int scat_blocks = (E + 7) / 8;

    // degrees (shared by both layers)
    deg_init<<<nb256, 256>>>(dinv, n);
    deg_count<<<eb256, 256>>>(dst, dinv, E);
    deg_finalize<<<nb256, 256>>>(dinv, n);

    // ---- layer 1: y1 = nan0(x)@W1 * dinv; agg1 = y1*dinv + scatter ----
    gemm128<<<gemm_blocks, 256>>>(x, W1, scsh, dinv, bufA, bufB, n, 1);
    edge_scatter<<<scat_blocks, 256>>>(bufA, src, dst, dinv, bufB, E);
    zero_kernel<<<1, 256>>>(stats, 256);
    bn_stats<<<512, 128>>>(bufB, stats, n);
    bn_finalize<<<1, 128>>>(stats, g1, be1, scsh, n);

    // ---- layer 2: A = relu(bn(agg1)) applied in gemm load ----
    gemm128<<<gemm_blocks, 256>>>(bufB, W2, scsh, dinv, bufA, bufC, n, 2);
    edge_scatter<<<scat_blocks, 256>>>(bufA, src, dst, dinv, bufC, E);
    zero_kernel<<<1, 256>>>(stats, 256);
    bn_stats<<<512, 128>>>(bufC, stats, n);
    bn_finalize<<<1, 128>>>(stats, g2, be2, scsh, n);

    // ---- pool (BN+ReLU fused) + classifier ----
    zero_kernel<<<(NGRAPH * HID + 255) / 256, 256>>>(pooled, NGRAPH * HID);
    zero_kernel<<<1, 64>>>(counts, NGRAPH);
    counts_kernel<<<64, 256>>>(batch, counts, n);
    pool_kernel<<<(n + 127) / 128, 128>>>(bufC, scsh, batch, pooled, n);
    classifier_kernel<<<1, 256>>>(pooled, counts, Wc1, bc1, Wc2, bc2, out);
}